// round 1
// baseline (speedup 1.0000x reference)
#include <cuda_runtime.h>

#define NB 512
#define NT 1024
#define NK 48
#define SSTART 46
#define SEND 47
#define NEGV (-10000.0f)
#define LOG2E 1.4426950408889634f
#define LN2F 0.6931471805599453f

// dyn smem: bp[NT*NK] u8 | aBuf[2*NK] f32 | vBuf[2*NK] f32 | red[2*NK] f32
#define SMEM_BYTES (NT*NK + 2*NK*4 + 2*NK*4 + 2*NK*4)

__device__ __forceinline__ float ex2f(float x) {
    float y; asm("ex2.approx.ftz.f32 %0, %1;" : "=f"(y) : "f"(x)); return y;
}
__device__ __forceinline__ float lg2f(float x) {
    float y; asm("lg2.approx.f32 %0, %1;" : "=f"(y) : "f"(x)); return y;
}

__global__ __launch_bounds__(64, 4)
void crf_kernel(const float* __restrict__ feats,
                const float* __restrict__ trans,
                float* __restrict__ out)
{
    extern __shared__ char sm[];
    unsigned char* bp = reinterpret_cast<unsigned char*>(sm);
    float* aBuf = reinterpret_cast<float*>(sm + NT*NK);  // [2][NK] log2-domain alpha
    float* vBuf = aBuf + 2*NK;                           // [2][NK] plain-domain viterbi
    float* red  = vBuf + 2*NK;                           // [2*NK] final reductions

    const int b = blockIdx.x;
    const int j = threadIdx.x;
    const float* f = feats + (size_t)b * NT * NK;

    float tl[NK];   // masked trans row j, scaled by log2(e)  (forward)
    float tw[NK];   // masked trans row j, plain              (viterbi, bit-exact)
    float featv = 0.f;
    if (j < NK) {
        #pragma unroll
        for (int p = 0; p < NK; ++p) {
            float t = trans[j*NK + p];
            if (j == SSTART) t = NEGV;   // no transition into START row
            if (p == SEND)   t = NEGV;   // no transition out of END column
            tw[p] = t;
            tl[p] = t * LOG2E;
        }
        aBuf[j] = (j == SSTART) ? 0.f : NEGV * LOG2E;
        vBuf[j] = (j == SSTART) ? 0.f : NEGV;
        featv = __ldg(f + j);
    }
    __syncthreads();

    float Csum = 0.f;   // accumulated log2-domain renormalization offset
    int cur = 0;
    #pragma unroll 1
    for (int t = 0; t < NT; ++t) {
        float featn = 0.f;
        if (j < NK && t + 1 < NT) featn = __ldg(f + (t+1)*NK + j);  // prefetch

        if (j < NK) {
            const float4* a4 = reinterpret_cast<const float4*>(aBuf + cur*NK);
            const float4* v4 = reinterpret_cast<const float4*>(vBuf + cur*NK);
            float s0 = 0.f, s1 = 0.f, s2 = 0.f, s3 = 0.f;
            float m0 = -3.4e38f, m1 = -3.4e38f, m2 = -3.4e38f, m3 = -3.4e38f;
            int   i0 = 0, i1 = 1, i2 = 2, i3 = 3;
            float a0v = 0.f;
            #pragma unroll
            for (int c = 0; c < NK/4; ++c) {
                float4 av = a4[c];
                float4 vv = v4[c];
                if (c == 0) a0v = av.x;
                // forward: sum_p exp2(alpha2[p] + tl[p])   (no per-row max needed:
                // alpha2 kept bounded by the running shift below)
                s0 += ex2f(av.x + tl[4*c+0]);
                s1 += ex2f(av.y + tl[4*c+1]);
                s2 += ex2f(av.z + tl[4*c+2]);
                s3 += ex2f(av.w + tl[4*c+3]);
                // viterbi: plain domain, same op order as reference -> bit-exact
                float y;
                y = vv.x + tw[4*c+0]; if (y > m0) { m0 = y; i0 = 4*c+0; }
                y = vv.y + tw[4*c+1]; if (y > m1) { m1 = y; i1 = 4*c+1; }
                y = vv.z + tw[4*c+2]; if (y > m2) { m2 = y; i2 = 4*c+2; }
                y = vv.w + tw[4*c+3]; if (y > m3) { m3 = y; i3 = 4*c+3; }
            }
            float s  = (s0 + s1) + (s2 + s3);
            float sh = fminf(fmaxf(a0v, -80.f), 80.f);  // renormalize near 0
            Csum += sh;
            float na = lg2f(s) + featv * LOG2E - sh;

            // merge 4 argmax chains with exact first-max tie-break (matches jnp.argmax)
            float bm = m0; int bi = i0;
            if (m1 > bm || (m1 == bm && i1 < bi)) { bm = m1; bi = i1; }
            if (m2 > bm || (m2 == bm && i2 < bi)) { bm = m2; bi = i2; }
            if (m3 > bm || (m3 == bm && i3 < bi)) { bm = m3; bi = i3; }
            float nv = bm + featv;   // emission added AFTER max (matches reference)

            bp[t*NK + j] = (unsigned char)bi;
            aBuf[(cur^1)*NK + j] = na;
            vBuf[(cur^1)*NK + j] = nv;
        }
        featv = featn;
        cur ^= 1;
        __syncthreads();
    }

    // ---- termination ----
    if (j < NK) {
        float te = trans[SEND*NK + j];
        if (j == SEND) te = NEGV;                 // column END masked
        red[j]      = aBuf[cur*NK + j] + te * LOG2E;  // forward terms (log2 domain)
        red[NK + j] = vBuf[cur*NK + j] + te;          // viterbi terms (plain, exact)
    }
    __syncthreads();

    if (j == 0) {
        // logz = logsumexp(alpha + trans[END])
        float m = -3.4e38f;
        #pragma unroll
        for (int p = 0; p < NK; ++p) m = fmaxf(m, red[p]);
        float s = 0.f;
        #pragma unroll
        for (int p = 0; p < NK; ++p) s += ex2f(red[p] - m);
        out[b] = (m + lg2f(s) + Csum) * LN2F;

        // viterbi terminal argmax (first-max) + backtrace through smem bptrs
        float bm = -3.4e38f; int last = 0;
        #pragma unroll
        for (int p = 0; p < NK; ++p) {
            float y = red[NK + p];
            if (y > bm) { bm = y; last = p; }
        }
        out[NB + b] = bm;

        float* po = out + 2*NB + (size_t)b * NT;
        int tag = last;
        #pragma unroll 1
        for (int t = NT - 1; t >= 0; --t) {
            po[t] = (float)tag;
            tag = bp[t*NK + tag];
        }
    }
}

extern "C" void kernel_launch(void* const* d_in, const int* in_sizes, int n_in,
                              void* d_out, int out_size)
{
    const float* feats = (const float*)d_in[0];
    const float* trans = (const float*)d_in[1];
    float* out = (float*)d_out;
    cudaFuncSetAttribute(crf_kernel, cudaFuncAttributeMaxDynamicSharedMemorySize,
                         SMEM_BYTES);
    crf_kernel<<<NB, 64, SMEM_BYTES>>>(feats, trans, out);
}